// round 1
// baseline (speedup 1.0000x reference)
#include <cuda_runtime.h>

#define N_TOK 32768
#define H_DIM 512
#define O_DIM 512
#define N_EXP 16

#define TM 128
#define TN 128
#define TK 16

// Scratch (no device allocs allowed in kernel_launch)
__device__ int g_expert_idx[N_TOK];
__device__ int g_counts[N_EXP];
__device__ int g_offsets[N_EXP + 1];
__device__ int g_fill[N_EXP];
__device__ int g_perm[N_TOK];

// ---------------------------------------------------------------------------
// 0) zero counters
// ---------------------------------------------------------------------------
__global__ void zero_kernel() {
    int t = threadIdx.x;
    if (t < N_EXP) { g_counts[t] = 0; g_fill[t] = 0; }
}

// ---------------------------------------------------------------------------
// 1) gate: logits = x @ Wg^T + bg ; expert = argmax (softmax is monotone)
//    one warp per token, Wg cached in smem (32 KB)
// ---------------------------------------------------------------------------
__global__ void gate_kernel(const float* __restrict__ x,
                            const float* __restrict__ Wg,
                            const float* __restrict__ bg) {
    __shared__ float sWg[N_EXP * H_DIM];
    int tid = threadIdx.x;
    for (int i = tid; i < N_EXP * H_DIM; i += 256) sWg[i] = Wg[i];
    __syncthreads();

    int warp = tid >> 5, lane = tid & 31;
    int base = blockIdx.x * 32 + warp * 4;   // 8 warps x 4 tokens

    for (int t = 0; t < 4; t++) {
        int n = base + t;
        const float* xr = x + (size_t)n * H_DIM;
        float acc[N_EXP];
        #pragma unroll
        for (int e = 0; e < N_EXP; e++) acc[e] = 0.f;

        #pragma unroll 4
        for (int h0 = 0; h0 < H_DIM; h0 += 32) {
            float xv = xr[h0 + lane];
            #pragma unroll
            for (int e = 0; e < N_EXP; e++)
                acc[e] = fmaf(xv, sWg[e * H_DIM + h0 + lane], acc[e]);
        }
        #pragma unroll
        for (int e = 0; e < N_EXP; e++) {
            #pragma unroll
            for (int off = 16; off; off >>= 1)
                acc[e] += __shfl_down_sync(0xffffffffu, acc[e], off);
        }
        if (lane == 0) {
            int best = 0; float bv = acc[0] + bg[0];
            #pragma unroll
            for (int e = 1; e < N_EXP; e++) {
                float v = acc[e] + bg[e];
                if (v > bv) { bv = v; best = e; }   // strict > keeps first max (argmax semantics)
            }
            g_expert_idx[n] = best;
            atomicAdd(&g_counts[best], 1);
        }
    }
}

// ---------------------------------------------------------------------------
// 2) exclusive scan over 16 counts
// ---------------------------------------------------------------------------
__global__ void scan_kernel() {
    if (threadIdx.x == 0) {
        int c = 0;
        g_offsets[0] = 0;
        for (int e = 0; e < N_EXP; e++) { c += g_counts[e]; g_offsets[e + 1] = c; }
    }
}

// ---------------------------------------------------------------------------
// 3) scatter token ids into per-expert buckets
// ---------------------------------------------------------------------------
__global__ void scatter_kernel() {
    int n = blockIdx.x * 256 + threadIdx.x;
    int e = g_expert_idx[n];
    int pos = atomicAdd(&g_fill[e], 1);
    g_perm[g_offsets[e] + pos] = n;
}

// ---------------------------------------------------------------------------
// 4) grouped SGEMM: for each expert, out[perm rows] = x[perm rows] @ We[e]^T + be[e]
//    128x128 tile, TK=16, 256 threads, 8x8 microtile per thread
// ---------------------------------------------------------------------------
__global__ void __launch_bounds__(256, 2) moe_gemm_kernel(
    const float* __restrict__ x, const float* __restrict__ We,
    const float* __restrict__ be, float* __restrict__ out)
{
    __shared__ float sA[TK][TM];
    __shared__ float sB[TK][TN];
    __shared__ int s_off[N_EXP + 1];

    int tid = threadIdx.x;
    if (tid <= N_EXP) s_off[tid] = g_offsets[tid];
    __syncthreads();

    // map blockIdx.y -> (expert, tile-within-expert)
    int e = -1, tile = 0;
    {
        int want = (int)blockIdx.y, cum = 0;
        #pragma unroll
        for (int i = 0; i < N_EXP; i++) {
            int nt = (s_off[i + 1] - s_off[i] + TM - 1) >> 7;
            if (e < 0 && want < cum + nt) { e = i; tile = want - cum; }
            cum += nt;
        }
    }
    if (e < 0) return;

    int off  = s_off[e];
    int cnt  = s_off[e + 1] - off;
    int row0 = tile * TM;

    int lrow = tid >> 2;     // 0..63
    int kq   = tid & 3;      // float4 column within TK

    bool va0 = (row0 + lrow)      < cnt;
    bool va1 = (row0 + lrow + 64) < cnt;
    const float* xa0 = va0 ? x + (size_t)g_perm[off + row0 + lrow]      * H_DIM + kq * 4 : x;
    const float* xa1 = va1 ? x + (size_t)g_perm[off + row0 + lrow + 64] * H_DIM + kq * 4 : x;
    const float* wb0 = We + ((size_t)e * O_DIM + blockIdx.x * TN + lrow) * H_DIM + kq * 4;
    const float* wb1 = wb0 + (size_t)64 * H_DIM;

    int ty = tid >> 4, tx = tid & 15;

    float acc[8][8];
    #pragma unroll
    for (int i = 0; i < 8; i++)
        #pragma unroll
        for (int j = 0; j < 8; j++) acc[i][j] = 0.f;

    float4 a0, a1, b0, b1;
    const float4 fz = make_float4(0.f, 0.f, 0.f, 0.f);
    a0 = va0 ? *(const float4*)(xa0) : fz;
    a1 = va1 ? *(const float4*)(xa1) : fz;
    b0 = *(const float4*)(wb0);
    b1 = *(const float4*)(wb1);

    #pragma unroll 1
    for (int kt = 0; kt < H_DIM / TK; kt++) {
        sA[kq * 4 + 0][lrow] = a0.x; sA[kq * 4 + 1][lrow] = a0.y;
        sA[kq * 4 + 2][lrow] = a0.z; sA[kq * 4 + 3][lrow] = a0.w;
        sA[kq * 4 + 0][lrow + 64] = a1.x; sA[kq * 4 + 1][lrow + 64] = a1.y;
        sA[kq * 4 + 2][lrow + 64] = a1.z; sA[kq * 4 + 3][lrow + 64] = a1.w;
        sB[kq * 4 + 0][lrow] = b0.x; sB[kq * 4 + 1][lrow] = b0.y;
        sB[kq * 4 + 2][lrow] = b0.z; sB[kq * 4 + 3][lrow] = b0.w;
        sB[kq * 4 + 0][lrow + 64] = b1.x; sB[kq * 4 + 1][lrow + 64] = b1.y;
        sB[kq * 4 + 2][lrow + 64] = b1.z; sB[kq * 4 + 3][lrow + 64] = b1.w;
        __syncthreads();

        if (kt + 1 < H_DIM / TK) {
            int k0 = (kt + 1) * TK;
            a0 = va0 ? *(const float4*)(xa0 + k0) : fz;
            a1 = va1 ? *(const float4*)(xa1 + k0) : fz;
            b0 = *(const float4*)(wb0 + k0);
            b1 = *(const float4*)(wb1 + k0);
        }

        #pragma unroll
        for (int kk = 0; kk < TK; kk++) {
            float4 ra0 = *(const float4*)(&sA[kk][ty * 4]);
            float4 ra1 = *(const float4*)(&sA[kk][ty * 4 + 64]);
            float4 rb0 = *(const float4*)(&sB[kk][tx * 4]);
            float4 rb1 = *(const float4*)(&sB[kk][tx * 4 + 64]);
            float ar[8] = {ra0.x, ra0.y, ra0.z, ra0.w, ra1.x, ra1.y, ra1.z, ra1.w};
            float br[8] = {rb0.x, rb0.y, rb0.z, rb0.w, rb1.x, rb1.y, rb1.z, rb1.w};
            #pragma unroll
            for (int i = 0; i < 8; i++)
                #pragma unroll
                for (int j = 0; j < 8; j++)
                    acc[i][j] = fmaf(ar[i], br[j], acc[i][j]);
        }
        __syncthreads();
    }

    // epilogue: add bias, scatter-store per token row
    int gc = blockIdx.x * TN + tx * 4;
    float4 bb0 = *(const float4*)(be + e * O_DIM + gc);
    float4 bb1 = *(const float4*)(be + e * O_DIM + gc + 64);

    #pragma unroll
    for (int i = 0; i < 8; i++) {
        int r = (i < 4) ? (ty * 4 + i) : (64 + ty * 4 + (i - 4));
        if (row0 + r < cnt) {
            int token = g_perm[off + row0 + r];
            float* po = out + (size_t)token * O_DIM + gc;
            float4 v0 = make_float4(acc[i][0] + bb0.x, acc[i][1] + bb0.y,
                                    acc[i][2] + bb0.z, acc[i][3] + bb0.w);
            float4 v1 = make_float4(acc[i][4] + bb1.x, acc[i][5] + bb1.y,
                                    acc[i][6] + bb1.z, acc[i][7] + bb1.w);
            *(float4*)(po)      = v0;
            *(float4*)(po + 64) = v1;
        }
    }
}

// ---------------------------------------------------------------------------
extern "C" void kernel_launch(void* const* d_in, const int* in_sizes, int n_in,
                              void* d_out, int out_size) {
    const float* x  = (const float*)d_in[0];
    const float* Wg = (const float*)d_in[1];
    const float* bg = (const float*)d_in[2];
    const float* We = (const float*)d_in[3];
    const float* be = (const float*)d_in[4];
    float* out = (float*)d_out;

    zero_kernel<<<1, 32>>>();
    gate_kernel<<<N_TOK / 32, 256>>>(x, Wg, bg);
    scan_kernel<<<1, 1>>>();
    scatter_kernel<<<N_TOK / 256, 256>>>();

    dim3 grid(O_DIM / TN, N_TOK / TM + N_EXP);   // max token tiles = 256 + 16 padding tiles
    moe_gemm_kernel<<<grid, 256>>>(x, We, be, out);
}

// round 7
// speedup vs baseline: 2.0218x; 2.0218x over previous
#include <cuda_runtime.h>
#include <cuda_bf16.h>
#include <cstdint>

#define N_TOK 32768
#define H_DIM 512
#define O_DIM 512
#define N_EXP 16
#define KTOT  1024          // stored doubled K (hi|lo)
#define KT    64            // bf16 per K-tile (128B rows)
#define NIT   24            // 3 phases x 8 tiles (hi*hi, lo*hi, hi*lo)
#define TM    128
#define TN    128
#define STAGES 3

// ---------------- scratch (device globals: no allocs allowed) ----------------
__device__ int g_expert_idx[N_TOK];
__device__ int g_counts[N_EXP];
__device__ int g_offsets[N_EXP + 1];
__device__ int g_fill[N_EXP];
__device__ int g_perm[N_TOK];
__device__ __nv_bfloat16 g_xs[(size_t)N_TOK * KTOT];            // 64 MB
__device__ __nv_bfloat16 g_ws[(size_t)N_EXP * O_DIM * KTOT];    // 16 MB

// ---------------- PTX helpers (plain sm_103-safe: no tcgen05) ----------------
__device__ __forceinline__ uint32_t smem_u32(const void* p) {
    uint32_t a;
    asm("{ .reg .u64 t; cvta.to.shared.u64 t, %1; cvt.u32.u64 %0, t; }" : "=r"(a) : "l"(p));
    return a;
}
#define SWZ128(o) ((o) ^ (((o) >> 3) & 0x70))

#define CP_ASYNC16(dst, src, sz) \
    asm volatile("cp.async.cg.shared.global [%0], [%1], 16, %2;" \
                 :: "r"(dst), "l"(src), "r"(sz) : "memory")
#define CP_COMMIT() asm volatile("cp.async.commit_group;" ::: "memory")
#define CP_WAIT(n)  asm volatile("cp.async.wait_group %0;" :: "n"(n) : "memory")

#define LDMX4(r0, r1, r2, r3, addr) \
    asm volatile("ldmatrix.sync.aligned.m8n8.x4.shared.b16 {%0,%1,%2,%3}, [%4];" \
                 : "=r"(r0), "=r"(r1), "=r"(r2), "=r"(r3) : "r"(addr))
#define LDMX2(r0, r1, addr) \
    asm volatile("ldmatrix.sync.aligned.m8n8.x2.shared.b16 {%0,%1}, [%2];" \
                 : "=r"(r0), "=r"(r1) : "r"(addr))

#define MMA16816(c, a, bq) \
    asm volatile("mma.sync.aligned.m16n8k16.row.col.f32.bf16.bf16.f32 " \
                 "{%0,%1,%2,%3}, {%4,%5,%6,%7}, {%8,%9}, {%0,%1,%2,%3};" \
                 : "+f"((c)[0]), "+f"((c)[1]), "+f"((c)[2]), "+f"((c)[3]) \
                 : "r"((a)[0]), "r"((a)[1]), "r"((a)[2]), "r"((a)[3]), \
                   "r"((bq)[0]), "r"((bq)[1]))

// ---------------------------------------------------------------------------
// 0) zero counters
// ---------------------------------------------------------------------------
__global__ void zero_kernel() {
    int t = threadIdx.x;
    if (t < N_EXP) { g_counts[t] = 0; g_fill[t] = 0; }
}

// ---------------------------------------------------------------------------
// 1) gate (argmax of logits) + fused bf16 hi/lo split of x into g_xs
// ---------------------------------------------------------------------------
__global__ void gate_kernel(const float* __restrict__ x,
                            const float* __restrict__ Wg,
                            const float* __restrict__ bg) {
    __shared__ float sWg[N_EXP * H_DIM];
    __shared__ int s_cnt[N_EXP];
    int tid = threadIdx.x;
    if (tid < N_EXP) s_cnt[tid] = 0;
    for (int i = tid; i < N_EXP * H_DIM; i += 256) sWg[i] = Wg[i];
    __syncthreads();

    int warp = tid >> 5, lane = tid & 31;
    int base = blockIdx.x * 32 + warp * 4;

    for (int t = 0; t < 4; t++) {
        int n = base + t;
        const float* xr = x + (size_t)n * H_DIM;
        __nv_bfloat16* xsr = g_xs + (size_t)n * KTOT;
        float acc[N_EXP];
        #pragma unroll
        for (int e = 0; e < N_EXP; e++) acc[e] = 0.f;

        #pragma unroll 4
        for (int h0 = 0; h0 < H_DIM; h0 += 32) {
            float xv = xr[h0 + lane];
            __nv_bfloat16 hi = __float2bfloat16(xv);
            float lo = xv - __bfloat162float(hi);
            xsr[h0 + lane] = hi;
            xsr[H_DIM + h0 + lane] = __float2bfloat16(lo);
            #pragma unroll
            for (int e = 0; e < N_EXP; e++)
                acc[e] = fmaf(xv, sWg[e * H_DIM + h0 + lane], acc[e]);
        }
        #pragma unroll
        for (int e = 0; e < N_EXP; e++) {
            #pragma unroll
            for (int off = 16; off; off >>= 1)
                acc[e] += __shfl_down_sync(0xffffffffu, acc[e], off);
        }
        if (lane == 0) {
            int best = 0; float bv = acc[0] + bg[0];
            #pragma unroll
            for (int e = 1; e < N_EXP; e++) {
                float v = acc[e] + bg[e];
                if (v > bv) { bv = v; best = e; }
            }
            g_expert_idx[n] = best;
            atomicAdd(&s_cnt[best], 1);
        }
    }
    __syncthreads();
    if (tid < N_EXP && s_cnt[tid]) atomicAdd(&g_counts[tid], s_cnt[tid]);
}

// ---------------------------------------------------------------------------
// 1b) split We into hi/lo bf16 g_ws
// ---------------------------------------------------------------------------
__global__ void convert_we_kernel(const float* __restrict__ We) {
    size_t idx = (size_t)blockIdx.x * 256 + threadIdx.x;
    float v = We[idx];
    size_t row = idx >> 9;
    size_t col = idx & 511;
    __nv_bfloat16 hi = __float2bfloat16(v);
    float lo = v - __bfloat162float(hi);
    g_ws[row * KTOT + col] = hi;
    g_ws[row * KTOT + H_DIM + col] = __float2bfloat16(lo);
}

// ---------------------------------------------------------------------------
// 2) exclusive scan over 16 counts
// ---------------------------------------------------------------------------
__global__ void scan_kernel() {
    if (threadIdx.x == 0) {
        int c = 0;
        g_offsets[0] = 0;
        for (int e = 0; e < N_EXP; e++) { c += g_counts[e]; g_offsets[e + 1] = c; }
    }
}

// ---------------------------------------------------------------------------
// 3) scatter with per-block aggregation
// ---------------------------------------------------------------------------
__global__ void scatter_kernel() {
    __shared__ int s_cnt[N_EXP], s_base[N_EXP];
    int tid = threadIdx.x;
    if (tid < N_EXP) s_cnt[tid] = 0;
    __syncthreads();
    int n = blockIdx.x * 256 + tid;
    int e = g_expert_idx[n];
    int loc = atomicAdd(&s_cnt[e], 1);
    __syncthreads();
    if (tid < N_EXP) s_base[tid] = atomicAdd(&g_fill[tid], s_cnt[tid]);
    __syncthreads();
    g_perm[g_offsets[e] + s_base[e] + loc] = n;
}

// ---------------------------------------------------------------------------
// 4) grouped bf16 HMMA GEMM, 3-term Markidis split:
//    acc = A_hi*B_hi + A_lo*B_hi + A_hi*B_lo   (24 K-tile pairs of 64)
//    128x128 tile, warp tile 64x32, mma.m16n8k16, 3-stage cp.async pipeline
// ---------------------------------------------------------------------------
#define SM_TOTAL (1024 + STAGES * 32768)

__global__ void __launch_bounds__(256) moe_gemm_mma(const float* __restrict__ be,
                                                    float* __restrict__ out) {
    extern __shared__ char smem[];
    uint32_t sbase = smem_u32(smem);
    int tid = threadIdx.x, wid = tid >> 5, lane = tid & 31;
    int* s_off = (int*)(smem + 64);
    int* s_perm = (int*)(smem + 512);

    if (tid <= N_EXP) s_off[tid] = g_offsets[tid];
    __syncthreads();

    // map blockIdx.y -> (expert, tile)
    int e = -1, tile = 0;
    {
        int want = (int)blockIdx.y, cum = 0;
        #pragma unroll
        for (int i = 0; i < N_EXP; i++) {
            int nt = (s_off[i + 1] - s_off[i] + TM - 1) >> 7;
            if (e < 0 && want < cum + nt) { e = i; tile = want - cum; }
            cum += nt;
        }
    }
    if (e < 0) return;

    int off = s_off[e];
    int cnt = s_off[e + 1] - off;
    int row0 = tile * TM;
    int bx = blockIdx.x;

    if (tid < TM) {
        int gr = row0 + tid;
        s_perm[tid] = (gr < cnt) ? g_perm[off + gr] : -1;
    }
    __syncthreads();

    // gmem->smem plumbing: each thread owns 4 rows (rbase+32j), one 16B seg
    int rbase = tid >> 3, seg = tid & 7;
    const __nv_bfloat16 *srcA[4], *srcB[4];
    uint32_t szA[4], sto[4];
    #pragma unroll
    for (int j = 0; j < 4; j++) {
        int r = rbase + 32 * j;
        int tok = s_perm[r];
        szA[j] = (tok >= 0) ? 16u : 0u;
        srcA[j] = g_xs + (size_t)(tok >= 0 ? tok : 0) * KTOT + seg * 8;
        srcB[j] = g_ws + ((size_t)e * O_DIM + bx * TN + r) * KTOT + seg * 8;
        sto[j] = SWZ128((uint32_t)(r * 128 + seg * 16));
    }

    // iteration kt in [0,24): phase p = kt>>3, t = kt&7
    //   A tile index ta = t + (p==1 ? 8 : 0)   (lo only in phase 1)
    //   B tile index tb = t + (p==2 ? 8 : 0)   (lo only in phase 2)
    #define ISSUE_TILE(kt, s) do {                                       \
        int p_ = (kt) >> 3, t_ = (kt) & 7;                               \
        int ta_ = t_ + ((p_ == 1) ? 8 : 0);                              \
        int tb_ = t_ + ((p_ == 2) ? 8 : 0);                              \
        uint32_t da_ = sbase + 1024 + (s) * 32768;                       \
        uint32_t db_ = da_ + 16384;                                      \
        _Pragma("unroll")                                                \
        for (int j_ = 0; j_ < 4; j_++) {                                 \
            CP_ASYNC16(da_ + sto[j_], srcA[j_] + ta_ * KT, szA[j_]);     \
            CP_ASYNC16(db_ + sto[j_], srcB[j_] + tb_ * KT, 16u);         \
        }                                                                \
        CP_COMMIT();                                                     \
    } while (0)

    ISSUE_TILE(0, 0);
    ISSUE_TILE(1, 1);
    ISSUE_TILE(2, 2);

    int wm = wid & 1;        // 2 M-halves of 64
    int wn = wid >> 1;       // 4 N-quarters of 32

    float acc[4][4][4];
    #pragma unroll
    for (int mi = 0; mi < 4; mi++)
        #pragma unroll
        for (int nj = 0; nj < 4; nj++)
            #pragma unroll
            for (int q = 0; q < 4; q++) acc[mi][nj][q] = 0.f;

    int sstage = 0;
    #pragma unroll 1
    for (int kt = 0; kt < NIT; kt++) {
        CP_WAIT(2);
        __syncthreads();

        uint32_t abase = sbase + 1024 + sstage * 32768;
        uint32_t bbase = abase + 16384;

        #pragma unroll
        for (int ks = 0; ks < 4; ks++) {
            uint32_t a[4][4], bq[4][2];
            #pragma unroll
            for (int mi = 0; mi < 4; mi++) {
                int m = wm * 64 + mi * 16 + (lane & 15);
                uint32_t byte = (uint32_t)(m * 128 + ks * 32 + (lane >> 4) * 16);
                LDMX4(a[mi][0], a[mi][1], a[mi][2], a[mi][3], abase + SWZ128(byte));
            }
            #pragma unroll
            for (int nj = 0; nj < 4; nj++) {
                int n = wn * 32 + nj * 8 + (lane & 7);
                uint32_t byte = (uint32_t)(n * 128 + ks * 32 + ((lane >> 3) & 1) * 16);
                LDMX2(bq[nj][0], bq[nj][1], bbase + SWZ128(byte));
            }
            #pragma unroll
            for (int mi = 0; mi < 4; mi++)
                #pragma unroll
                for (int nj = 0; nj < 4; nj++)
                    MMA16816(acc[mi][nj], a[mi], bq[nj]);
        }
        __syncthreads();

        if (kt + STAGES < NIT) ISSUE_TILE(kt + STAGES, sstage);
        sstage = (sstage + 1 == STAGES) ? 0 : sstage + 1;
    }
    CP_WAIT(0);

    // epilogue: bias + gathered v2 stores
    float2 bias[4];
    {
        const float* pb = be + e * O_DIM + bx * TN + wn * 32 + (lane & 3) * 2;
        #pragma unroll
        for (int nj = 0; nj < 4; nj++)
            bias[nj] = *(const float2*)(pb + nj * 8);
    }
    #pragma unroll
    for (int mi = 0; mi < 4; mi++) {
        int mr = wm * 64 + mi * 16 + (lane >> 2);
        #pragma unroll
        for (int h = 0; h < 2; h++) {
            int m = mr + 8 * h;
            int tok = s_perm[m];
            if (tok >= 0) {
                float* po = out + (size_t)tok * O_DIM + bx * TN + wn * 32 + (lane & 3) * 2;
                #pragma unroll
                for (int nj = 0; nj < 4; nj++) {
                    float2 v;
                    v.x = acc[mi][nj][2 * h + 0] + bias[nj].x;
                    v.y = acc[mi][nj][2 * h + 1] + bias[nj].y;
                    *(float2*)(po + nj * 8) = v;
                }
            }
        }
    }
}

// ---------------------------------------------------------------------------
extern "C" void kernel_launch(void* const* d_in, const int* in_sizes, int n_in,
                              void* d_out, int out_size) {
    const float* x  = (const float*)d_in[0];
    const float* Wg = (const float*)d_in[1];
    const float* bg = (const float*)d_in[2];
    const float* We = (const float*)d_in[3];
    const float* be = (const float*)d_in[4];
    float* out = (float*)d_out;

    cudaFuncSetAttribute(moe_gemm_mma, cudaFuncAttributeMaxDynamicSharedMemorySize, SM_TOTAL);

    zero_kernel<<<1, 32>>>();
    gate_kernel<<<N_TOK / 32, 256>>>(x, Wg, bg);
    convert_we_kernel<<<(N_EXP * O_DIM * H_DIM) / 256, 256>>>(We);
    scan_kernel<<<1, 1>>>();
    scatter_kernel<<<N_TOK / 256, 256>>>();

    dim3 grid(O_DIM / TN, N_TOK / TM + N_EXP);
    moe_gemm_mma<<<grid, 256, SM_TOTAL>>>(be, out);
}

// round 9
// speedup vs baseline: 2.4443x; 1.2090x over previous
#include <cuda_runtime.h>
#include <cuda_fp16.h>
#include <cstdint>

#define N_TOK 32768
#define H_DIM 512
#define O_DIM 512
#define N_EXP 16
#define KTOT  1024          // stored doubled K (hi|lo) in fp16
#define KT    64            // fp16 per K-tile (128B rows)
#define NIT   16            // diagonal: tile t of A pairs tile t of B
#define TM    128
#define TN    128
#define STAGES 3

// ---------------- scratch (device globals: no allocs allowed) ----------------
__device__ int g_expert_idx[N_TOK];
__device__ int g_counts[N_EXP];
__device__ int g_offsets[N_EXP + 1];
__device__ int g_fill[N_EXP];
__device__ int g_perm[N_TOK];
__device__ __half g_xs[(size_t)N_TOK * KTOT];            // 64 MB
__device__ __half g_ws[(size_t)N_EXP * O_DIM * KTOT];    // 16 MB

// ---------------- PTX helpers (plain sm_103-safe) ----------------
__device__ __forceinline__ uint32_t smem_u32(const void* p) {
    uint32_t a;
    asm("{ .reg .u64 t; cvta.to.shared.u64 t, %1; cvt.u32.u64 %0, t; }" : "=r"(a) : "l"(p));
    return a;
}
#define SWZ128(o) ((o) ^ (((o) >> 3) & 0x70))

#define CP_ASYNC16(dst, src, sz) \
    asm volatile("cp.async.cg.shared.global [%0], [%1], 16, %2;" \
                 :: "r"(dst), "l"(src), "r"(sz) : "memory")
#define CP_COMMIT() asm volatile("cp.async.commit_group;" ::: "memory")
#define CP_WAIT(n)  asm volatile("cp.async.wait_group %0;" :: "n"(n) : "memory")

#define LDMX4(r0, r1, r2, r3, addr) \
    asm volatile("ldmatrix.sync.aligned.m8n8.x4.shared.b16 {%0,%1,%2,%3}, [%4];" \
                 : "=r"(r0), "=r"(r1), "=r"(r2), "=r"(r3) : "r"(addr))
#define LDMX2(r0, r1, addr) \
    asm volatile("ldmatrix.sync.aligned.m8n8.x2.shared.b16 {%0,%1}, [%2];" \
                 : "=r"(r0), "=r"(r1) : "r"(addr))

#define MMA16816(c, a, bq) \
    asm volatile("mma.sync.aligned.m16n8k16.row.col.f32.f16.f16.f32 " \
                 "{%0,%1,%2,%3}, {%4,%5,%6,%7}, {%8,%9}, {%0,%1,%2,%3};" \
                 : "+f"((c)[0]), "+f"((c)[1]), "+f"((c)[2]), "+f"((c)[3]) \
                 : "r"((a)[0]), "r"((a)[1]), "r"((a)[2]), "r"((a)[3]), \
                   "r"((bq)[0]), "r"((bq)[1]))

// ---------------------------------------------------------------------------
// 0) zero counters
// ---------------------------------------------------------------------------
__global__ void zero_kernel() {
    int t = threadIdx.x;
    if (t < N_EXP) { g_counts[t] = 0; g_fill[t] = 0; }
}

// ---------------------------------------------------------------------------
// 1) gate (argmax of logits) + fused fp16 hi/lo split of x into g_xs
// ---------------------------------------------------------------------------
__global__ void gate_kernel(const float* __restrict__ x,
                            const float* __restrict__ Wg,
                            const float* __restrict__ bg) {
    __shared__ float sWg[N_EXP * H_DIM];
    __shared__ int s_cnt[N_EXP];
    int tid = threadIdx.x;
    if (tid < N_EXP) s_cnt[tid] = 0;
    for (int i = tid; i < N_EXP * H_DIM; i += 256) sWg[i] = Wg[i];
    __syncthreads();

    int warp = tid >> 5, lane = tid & 31;
    int base = blockIdx.x * 32 + warp * 4;

    for (int t = 0; t < 4; t++) {
        int n = base + t;
        const float* xr = x + (size_t)n * H_DIM;
        __half* xsr = g_xs + (size_t)n * KTOT;
        float acc[N_EXP];
        #pragma unroll
        for (int e = 0; e < N_EXP; e++) acc[e] = 0.f;

        #pragma unroll 4
        for (int h0 = 0; h0 < H_DIM; h0 += 32) {
            float xv = xr[h0 + lane];
            __half hi = __float2half(xv);
            float lo = xv - __half2float(hi);
            xsr[h0 + lane] = hi;
            xsr[H_DIM + h0 + lane] = __float2half(lo);
            #pragma unroll
            for (int e = 0; e < N_EXP; e++)
                acc[e] = fmaf(xv, sWg[e * H_DIM + h0 + lane], acc[e]);
        }
        #pragma unroll
        for (int e = 0; e < N_EXP; e++) {
            #pragma unroll
            for (int off = 16; off; off >>= 1)
                acc[e] += __shfl_down_sync(0xffffffffu, acc[e], off);
        }
        if (lane == 0) {
            int best = 0; float bv = acc[0] + bg[0];
            #pragma unroll
            for (int e = 1; e < N_EXP; e++) {
                float v = acc[e] + bg[e];
                if (v > bv) { bv = v; best = e; }
            }
            g_expert_idx[n] = best;
            atomicAdd(&s_cnt[best], 1);
        }
    }
    __syncthreads();
    if (tid < N_EXP && s_cnt[tid]) atomicAdd(&g_counts[tid], s_cnt[tid]);
}

// ---------------------------------------------------------------------------
// 1b) split We into hi/lo fp16 g_ws
// ---------------------------------------------------------------------------
__global__ void convert_we_kernel(const float* __restrict__ We) {
    size_t idx = (size_t)blockIdx.x * 256 + threadIdx.x;
    float v = We[idx];
    size_t row = idx >> 9;
    size_t col = idx & 511;
    __half hi = __float2half(v);
    float lo = v - __half2float(hi);
    g_ws[row * KTOT + col] = hi;
    g_ws[row * KTOT + H_DIM + col] = __float2half(lo);
}

// ---------------------------------------------------------------------------
// 2) exclusive scan over 16 counts
// ---------------------------------------------------------------------------
__global__ void scan_kernel() {
    if (threadIdx.x == 0) {
        int c = 0;
        g_offsets[0] = 0;
        for (int e = 0; e < N_EXP; e++) { c += g_counts[e]; g_offsets[e + 1] = c; }
    }
}

// ---------------------------------------------------------------------------
// 3) scatter with per-block aggregation
// ---------------------------------------------------------------------------
__global__ void scatter_kernel() {
    __shared__ int s_cnt[N_EXP], s_base[N_EXP];
    int tid = threadIdx.x;
    if (tid < N_EXP) s_cnt[tid] = 0;
    __syncthreads();
    int n = blockIdx.x * 256 + tid;
    int e = g_expert_idx[n];
    int loc = atomicAdd(&s_cnt[e], 1);
    __syncthreads();
    if (tid < N_EXP) s_base[tid] = atomicAdd(&g_fill[tid], s_cnt[tid]);
    __syncthreads();
    g_perm[g_offsets[e] + s_base[e] + loc] = n;
}

// ---------------------------------------------------------------------------
// 4) grouped fp16 HMMA GEMM, 2-term diagonal split over K=1024:
//    acc = A_hi*B_hi + A_lo*B_lo  (cross terms ~2^-11 -> rel_err ~3e-4)
//    128x128 tile, warp tile 64x32, mma.m16n8k16, 3-stage cp.async pipeline
// ---------------------------------------------------------------------------
#define SM_TOTAL (1024 + STAGES * 32768)

__global__ void __launch_bounds__(256) moe_gemm_mma(const float* __restrict__ be,
                                                    float* __restrict__ out) {
    extern __shared__ char smem[];
    uint32_t sbase = smem_u32(smem);
    int tid = threadIdx.x, wid = tid >> 5, lane = tid & 31;
    int* s_off = (int*)(smem + 64);
    int* s_perm = (int*)(smem + 512);

    if (tid <= N_EXP) s_off[tid] = g_offsets[tid];
    __syncthreads();

    // map blockIdx.y -> (expert, tile)
    int e = -1, tile = 0;
    {
        int want = (int)blockIdx.y, cum = 0;
        #pragma unroll
        for (int i = 0; i < N_EXP; i++) {
            int nt = (s_off[i + 1] - s_off[i] + TM - 1) >> 7;
            if (e < 0 && want < cum + nt) { e = i; tile = want - cum; }
            cum += nt;
        }
    }
    if (e < 0) return;

    int off = s_off[e];
    int cnt = s_off[e + 1] - off;
    int row0 = tile * TM;
    int bx = blockIdx.x;

    if (tid < TM) {
        int gr = row0 + tid;
        s_perm[tid] = (gr < cnt) ? g_perm[off + gr] : -1;
    }
    __syncthreads();

    // gmem->smem plumbing: each thread owns 4 rows (rbase+32j), one 16B seg
    int rbase = tid >> 3, seg = tid & 7;
    const __half *srcA[4], *srcB[4];
    uint32_t szA[4], sto[4];
    #pragma unroll
    for (int j = 0; j < 4; j++) {
        int r = rbase + 32 * j;
        int tok = s_perm[r];
        szA[j] = (tok >= 0) ? 16u : 0u;
        srcA[j] = g_xs + (size_t)(tok >= 0 ? tok : 0) * KTOT + seg * 8;
        srcB[j] = g_ws + ((size_t)e * O_DIM + bx * TN + r) * KTOT + seg * 8;
        sto[j] = SWZ128((uint32_t)(r * 128 + seg * 16));
    }

    #define ISSUE_TILE(kt, s) do {                                       \
        uint32_t da_ = sbase + 1024 + (s) * 32768;                       \
        uint32_t db_ = da_ + 16384;                                      \
        _Pragma("unroll")                                                \
        for (int j_ = 0; j_ < 4; j_++) {                                 \
            CP_ASYNC16(da_ + sto[j_], srcA[j_] + (kt) * KT, szA[j_]);    \
            CP_ASYNC16(db_ + sto[j_], srcB[j_] + (kt) * KT, 16u);        \
        }                                                                \
        CP_COMMIT();                                                     \
    } while (0)

    ISSUE_TILE(0, 0);
    ISSUE_TILE(1, 1);
    ISSUE_TILE(2, 2);

    int wm = wid & 1;        // 2 M-halves of 64
    int wn = wid >> 1;       // 4 N-quarters of 32

    float acc[4][4][4];
    #pragma unroll
    for (int mi = 0; mi < 4; mi++)
        #pragma unroll
        for (int nj = 0; nj < 4; nj++)
            #pragma unroll
            for (int q = 0; q < 4; q++) acc[mi][nj][q] = 0.f;

    int sstage = 0;
    #pragma unroll 1
    for (int kt = 0; kt < NIT; kt++) {
        CP_WAIT(2);
        __syncthreads();

        uint32_t abase = sbase + 1024 + sstage * 32768;
        uint32_t bbase = abase + 16384;

        #pragma unroll
        for (int ks = 0; ks < 4; ks++) {
            uint32_t a[4][4], bq[4][2];
            #pragma unroll
            for (int mi = 0; mi < 4; mi++) {
                int m = wm * 64 + mi * 16 + (lane & 15);
                uint32_t byte = (uint32_t)(m * 128 + ks * 32 + (lane >> 4) * 16);
                LDMX4(a[mi][0], a[mi][1], a[mi][2], a[mi][3], abase + SWZ128(byte));
            }
            #pragma unroll
            for (int nj = 0; nj < 4; nj++) {
                int n = wn * 32 + nj * 8 + (lane & 7);
                uint32_t byte = (uint32_t)(n * 128 + ks * 32 + ((lane >> 3) & 1) * 16);
                LDMX2(bq[nj][0], bq[nj][1], bbase + SWZ128(byte));
            }
            #pragma unroll
            for (int mi = 0; mi < 4; mi++)
                #pragma unroll
                for (int nj = 0; nj < 4; nj++)
                    MMA16816(acc[mi][nj], a[mi], bq[nj]);
        }
        __syncthreads();

        if (kt + STAGES < NIT) ISSUE_TILE(kt + STAGES, sstage);
        sstage = (sstage + 1 == STAGES) ? 0 : sstage + 1;
    }
    CP_WAIT(0);

    // epilogue: bias + gathered v2 stores
    float2 bias[4];
    {
        const float* pb = be + e * O_DIM + bx * TN + wn * 32 + (lane & 3) * 2;
        #pragma unroll
        for (int nj = 0; nj < 4; nj++)
            bias[nj] = *(const float2*)(pb + nj * 8);
    }
    #pragma unroll
    for (int mi = 0; mi < 4; mi++) {
        int mr = wm * 64 + mi * 16 + (lane >> 2);
        #pragma unroll
        for (int h = 0; h < 2; h++) {
            int m = mr + 8 * h;
            int tok = s_perm[m];
            if (tok >= 0) {
                float* po = out + (size_t)tok * O_DIM + bx * TN + wn * 32 + (lane & 3) * 2;
                #pragma unroll
                for (int nj = 0; nj < 4; nj++) {
                    float2 v;
                    v.x = acc[mi][nj][2 * h + 0] + bias[nj].x;
                    v.y = acc[mi][nj][2 * h + 1] + bias[nj].y;
                    *(float2*)(po + nj * 8) = v;
                }
            }
        }
    }
}

// ---------------------------------------------------------------------------
extern "C" void kernel_launch(void* const* d_in, const int* in_sizes, int n_in,
                              void* d_out, int out_size) {
    const float* x  = (const float*)d_in[0];
    const float* Wg = (const float*)d_in[1];
    const float* bg = (const float*)d_in[2];
    const float* We = (const float*)d_in[3];
    const float* be = (const float*)d_in[4];
    float* out = (float*)d_out;

    cudaFuncSetAttribute(moe_gemm_mma, cudaFuncAttributeMaxDynamicSharedMemorySize, SM_TOTAL);

    zero_kernel<<<1, 32>>>();
    gate_kernel<<<N_TOK / 32, 256>>>(x, Wg, bg);
    convert_we_kernel<<<(N_EXP * O_DIM * H_DIM) / 256, 256>>>(We);
    scan_kernel<<<1, 1>>>();
    scatter_kernel<<<N_TOK / 256, 256>>>();

    dim3 grid(O_DIM / TN, N_TOK / TM + N_EXP);
    moe_gemm_mma<<<grid, 256, SM_TOTAL>>>(be, out);
}

// round 12
// speedup vs baseline: 2.5513x; 1.0438x over previous
#include <cuda_runtime.h>
#include <cuda_fp16.h>
#include <cstdint>

#define N_TOK 32768
#define H_DIM 512
#define O_DIM 512
#define N_EXP 16
#define KTOT  1024          // stored doubled K (hi|lo) in fp16
#define KT    64            // fp16 per K-tile (128B rows)
#define NIT   16            // diagonal: tile t of A pairs tile t of B
#define TM    128
#define TN    128
#define STAGES 4

// ---------------- scratch ----------------
__device__ int g_expert_idx[N_TOK];
__device__ int g_counts[N_EXP];
__device__ int g_fill[N_EXP];
__device__ int g_perm[N_TOK];
__device__ __half g_xs[(size_t)N_TOK * KTOT];            // 64 MB
__device__ __half g_ws[(size_t)N_EXP * O_DIM * KTOT];    // 16 MB

// ---------------- PTX helpers ----------------
__device__ __forceinline__ uint32_t smem_u32(const void* p) {
    uint32_t a;
    asm("{ .reg .u64 t; cvta.to.shared.u64 t, %1; cvt.u32.u64 %0, t; }" : "=r"(a) : "l"(p));
    return a;
}
#define SWZ128(o) ((o) ^ (((o) >> 3) & 0x70))

#define CP_ASYNC16(dst, src, sz) \
    asm volatile("cp.async.cg.shared.global [%0], [%1], 16, %2;" \
                 :: "r"(dst), "l"(src), "r"(sz) : "memory")
#define CP_COMMIT() asm volatile("cp.async.commit_group;" ::: "memory")
#define CP_WAIT(n)  asm volatile("cp.async.wait_group %0;" :: "n"(n) : "memory")

#define LDMX4(r0, r1, r2, r3, addr) \
    asm volatile("ldmatrix.sync.aligned.m8n8.x4.shared.b16 {%0,%1,%2,%3}, [%4];" \
                 : "=r"(r0), "=r"(r1), "=r"(r2), "=r"(r3) : "r"(addr))
#define LDMX2(r0, r1, addr) \
    asm volatile("ldmatrix.sync.aligned.m8n8.x2.shared.b16 {%0,%1}, [%2];" \
                 : "=r"(r0), "=r"(r1) : "r"(addr))

#define MMA16816(c, a, bq) \
    asm volatile("mma.sync.aligned.m16n8k16.row.col.f32.f16.f16.f32 " \
                 "{%0,%1,%2,%3}, {%4,%5,%6,%7}, {%8,%9}, {%0,%1,%2,%3};" \
                 : "+f"((c)[0]), "+f"((c)[1]), "+f"((c)[2]), "+f"((c)[3]) \
                 : "r"((a)[0]), "r"((a)[1]), "r"((a)[2]), "r"((a)[3]), \
                   "r"((bq)[0]), "r"((bq)[1]))

// ---------------------------------------------------------------------------
// 0) zero counters
// ---------------------------------------------------------------------------
__global__ void zero_kernel() {
    int t = threadIdx.x;
    if (t < N_EXP) { g_counts[t] = 0; g_fill[t] = 0; }
}

// ---------------------------------------------------------------------------
// 1) gate (argmax of logits) + fused fp16 hi/lo split of x (half2 stores)
// ---------------------------------------------------------------------------
__global__ void gate_kernel(const float* __restrict__ x,
                            const float* __restrict__ Wg,
                            const float* __restrict__ bg) {
    __shared__ float sWg[N_EXP * H_DIM];
    __shared__ int s_cnt[N_EXP];
    int tid = threadIdx.x;
    if (tid < N_EXP) s_cnt[tid] = 0;
    for (int i = tid; i < N_EXP * H_DIM; i += 256) sWg[i] = Wg[i];
    __syncthreads();

    int warp = tid >> 5, lane = tid & 31;
    int base = blockIdx.x * 32 + warp * 4;

    for (int t = 0; t < 4; t++) {
        int n = base + t;
        const float* xr = x + (size_t)n * H_DIM;
        __half* xsr = g_xs + (size_t)n * KTOT;
        float acc[N_EXP];
        #pragma unroll
        for (int e = 0; e < N_EXP; e++) acc[e] = 0.f;

        #pragma unroll 2
        for (int h0 = 0; h0 < H_DIM; h0 += 64) {
            int c = h0 + 2 * lane;
            float2 xv = *(const float2*)(xr + c);
            __half2 hi2 = __floats2half2_rn(xv.x, xv.y);
            float2 hf = __half22float2(hi2);
            __half2 lo2 = __floats2half2_rn(xv.x - hf.x, xv.y - hf.y);
            *(__half2*)(xsr + c) = hi2;
            *(__half2*)(xsr + H_DIM + c) = lo2;
            #pragma unroll
            for (int e = 0; e < N_EXP; e++) {
                float2 w = *(const float2*)(&sWg[e * H_DIM + c]);
                acc[e] = fmaf(xv.x, w.x, fmaf(xv.y, w.y, acc[e]));
            }
        }
        #pragma unroll
        for (int e = 0; e < N_EXP; e++) {
            #pragma unroll
            for (int off = 16; off; off >>= 1)
                acc[e] += __shfl_down_sync(0xffffffffu, acc[e], off);
        }
        if (lane == 0) {
            int best = 0; float bv = acc[0] + bg[0];
            #pragma unroll
            for (int e = 1; e < N_EXP; e++) {
                float v = acc[e] + bg[e];
                if (v > bv) { bv = v; best = e; }
            }
            g_expert_idx[n] = best;
            atomicAdd(&s_cnt[best], 1);
        }
    }
    __syncthreads();
    if (tid < N_EXP && s_cnt[tid]) atomicAdd(&g_counts[tid], s_cnt[tid]);
}

// ---------------------------------------------------------------------------
// 1b) split We into hi/lo fp16 (float2 loads, half2 stores)
// ---------------------------------------------------------------------------
__global__ void convert_we_kernel(const float* __restrict__ We) {
    size_t i = (size_t)blockIdx.x * 256 + threadIdx.x;   // over E*O*H/2
    float2 v = *(const float2*)(We + 2 * i);
    size_t row = i >> 8;           // (2i)>>9
    size_t col = (2 * i) & 511;
    __half2 hi2 = __floats2half2_rn(v.x, v.y);
    float2 hf = __half22float2(hi2);
    __half2 lo2 = __floats2half2_rn(v.x - hf.x, v.y - hf.y);
    *(__half2*)(g_ws + row * KTOT + col) = hi2;
    *(__half2*)(g_ws + row * KTOT + H_DIM + col) = lo2;
}

// ---------------------------------------------------------------------------
// 2) scatter with per-block aggregation + local prefix (no scan kernel)
// ---------------------------------------------------------------------------
__global__ void scatter_kernel() {
    __shared__ int s_cnt[N_EXP], s_base[N_EXP], s_offl[N_EXP];
    int tid = threadIdx.x;
    if (tid < N_EXP) s_cnt[tid] = 0;
    __syncthreads();
    int n = blockIdx.x * 256 + tid;
    int e = g_expert_idx[n];
    int loc = atomicAdd(&s_cnt[e], 1);
    __syncthreads();
    if (tid < N_EXP) s_base[tid] = atomicAdd(&g_fill[tid], s_cnt[tid]);
    if (tid == 0) {
        int c = 0;
        #pragma unroll
        for (int i = 0; i < N_EXP; i++) { s_offl[i] = c; c += g_counts[i]; }
    }
    __syncthreads();
    g_perm[s_offl[e] + s_base[e] + loc] = n;
}

// ---------------------------------------------------------------------------
// 3) grouped fp16 HMMA GEMM, 2-term diagonal split over K=1024.
//    Single-sync multistage mainloop (S=4), register ping-pong fragments.
// ---------------------------------------------------------------------------
#define SM_TOTAL (1024 + STAGES * 32768)

__global__ void __launch_bounds__(256, 1) moe_gemm_mma(const float* __restrict__ be,
                                                       float* __restrict__ out) {
    extern __shared__ char smem[];
    uint32_t sbase = smem_u32(smem);
    int tid = threadIdx.x, wid = tid >> 5, lane = tid & 31;
    int* s_off = (int*)(smem + 64);
    int* s_perm = (int*)(smem + 512);

    if (tid == 0) {
        int c = 0;
        s_off[0] = 0;
        #pragma unroll
        for (int i = 0; i < N_EXP; i++) { c += g_counts[i]; s_off[i + 1] = c; }
    }
    __syncthreads();

    // map blockIdx.y -> (expert, tile)
    int e = -1, tile = 0;
    {
        int want = (int)blockIdx.y, cum = 0;
        #pragma unroll
        for (int i = 0; i < N_EXP; i++) {
            int nt = (s_off[i + 1] - s_off[i] + TM - 1) >> 7;
            if (e < 0 && want < cum + nt) { e = i; tile = want - cum; }
            cum += nt;
        }
    }
    if (e < 0) return;

    int off = s_off[e];
    int cnt = s_off[e + 1] - off;
    int row0 = tile * TM;
    int bx = blockIdx.x;

    if (tid < TM) {
        int gr = row0 + tid;
        s_perm[tid] = (gr < cnt) ? g_perm[off + gr] : -1;
    }
    __syncthreads();

    // gmem->smem plumbing: each thread owns 4 rows (rbase+32j), one 16B seg
    int rbase = tid >> 3, seg = tid & 7;
    const __half *srcA[4], *srcB[4];
    uint32_t szA[4], sto[4];
    #pragma unroll
    for (int j = 0; j < 4; j++) {
        int r = rbase + 32 * j;
        int tok = s_perm[r];
        szA[j] = (tok >= 0) ? 16u : 0u;
        srcA[j] = g_xs + (size_t)(tok >= 0 ? tok : 0) * KTOT + seg * 8;
        srcB[j] = g_ws + ((size_t)e * O_DIM + bx * TN + r) * KTOT + seg * 8;
        sto[j] = SWZ128((uint32_t)(r * 128 + seg * 16));
    }

    #define ISSUE_TILE(kt, s) do {                                       \
        uint32_t da_ = sbase + 1024 + (s) * 32768;                       \
        uint32_t db_ = da_ + 16384;                                      \
        _Pragma("unroll")                                                \
        for (int j_ = 0; j_ < 4; j_++) {                                 \
            CP_ASYNC16(da_ + sto[j_], srcA[j_] + (kt) * KT, szA[j_]);    \
            CP_ASYNC16(db_ + sto[j_], srcB[j_] + (kt) * KT, 16u);        \
        }                                                                \
        CP_COMMIT();                                                     \
    } while (0)

    // prologue: S-1 = 3 tiles
    ISSUE_TILE(0, 0);
    ISSUE_TILE(1, 1);
    ISSUE_TILE(2, 2);

    int wm = wid & 1;        // 2 M-halves of 64
    int wn = wid >> 1;       // 4 N-quarters of 32

    float acc[4][4][4];
    #pragma unroll
    for (int mi = 0; mi < 4; mi++)
        #pragma unroll
        for (int nj = 0; nj < 4; nj++)
            #pragma unroll
            for (int q = 0; q < 4; q++) acc[mi][nj][q] = 0.f;

    #define LOAD_FRAGS(ab, bb, ks_) do {                                          \
        _Pragma("unroll")                                                         \
        for (int mi_ = 0; mi_ < 4; mi_++) {                                       \
            int m_ = wm * 64 + mi_ * 16 + (lane & 15);                            \
            uint32_t byte_ = (uint32_t)(m_ * 128 + (ks_) * 32 + (lane >> 4) * 16);\
            LDMX4((ab)[mi_][0], (ab)[mi_][1], (ab)[mi_][2], (ab)[mi_][3],         \
                  abase + SWZ128(byte_));                                         \
        }                                                                         \
        _Pragma("unroll")                                                         \
        for (int nj_ = 0; nj_ < 4; nj_++) {                                       \
            int n_ = wn * 32 + nj_ * 8 + (lane & 7);                              \
            uint32_t byte_ = (uint32_t)(n_ * 128 + (ks_) * 32 + ((lane >> 3) & 1) * 16); \
            LDMX2((bb)[nj_][0], (bb)[nj_][1], bbase + SWZ128(byte_));             \
        }                                                                         \
    } while (0)

    #pragma unroll 1
    for (int kt = 0; kt < NIT; kt++) {
        CP_WAIT(2);
        __syncthreads();
        // stage (kt+3)&3 == (kt-1)&3 was fully consumed before this barrier
        if (kt + 3 < NIT) ISSUE_TILE(kt + 3, (kt + 3) & 3);

        uint32_t abase = sbase + 1024 + (kt & 3) * 32768;
        uint32_t bbase = abase + 16384;

        uint32_t a[2][4][4], bq[2][4][2];
        LOAD_FRAGS(a[0], bq[0], 0);
        #pragma unroll
        for (int ks = 0; ks < 4; ks++) {
            if (ks < 3) LOAD_FRAGS(a[(ks + 1) & 1], bq[(ks + 1) & 1], ks + 1);
            #pragma unroll
            for (int mi = 0; mi < 4; mi++)
                #pragma unroll
                for (int nj = 0; nj < 4; nj++)
                    MMA16816(acc[mi][nj], a[ks & 1][mi], bq[ks & 1][nj]);
        }
    }
    CP_WAIT(0);

    // epilogue: bias + gathered v2 stores
    float2 bias[4];
    {
        const float* pb = be + e * O_DIM + bx * TN + wn * 32 + (lane & 3) * 2;
        #pragma unroll
        for (int nj = 0; nj < 4; nj++)
            bias[nj] = *(const float2*)(pb + nj * 8);
    }
    #pragma unroll
    for (int mi = 0; mi < 4; mi++) {
        int mr = wm * 64 + mi * 16 + (lane >> 2);
        #pragma unroll
        for (int h = 0; h < 2; h++) {
            int m = mr + 8 * h;
            int tok = s_perm[m];
            if (tok >= 0) {
                float* po = out + (size_t)tok * O_DIM + bx * TN + wn * 32 + (lane & 3) * 2;
                #pragma unroll
                for (int nj = 0; nj < 4; nj++) {
                    float2 v;
                    v.x = acc[mi][nj][2 * h + 0] + bias[nj].x;
                    v.y = acc[mi][nj][2 * h + 1] + bias[nj].y;
                    *(float2*)(po + nj * 8) = v;
                }
            }
        }
    }
}

// ---------------------------------------------------------------------------
extern "C" void kernel_launch(void* const* d_in, const int* in_sizes, int n_in,
                              void* d_out, int out_size) {
    const float* x  = (const float*)d_in[0];
    const float* Wg = (const float*)d_in[1];
    const float* bg = (const float*)d_in[2];
    const float* We = (const float*)d_in[3];
    const float* be = (const float*)d_in[4];
    float* out = (float*)d_out;

    cudaFuncSetAttribute(moe_gemm_mma, cudaFuncAttributeMaxDynamicSharedMemorySize, SM_TOTAL);

    zero_kernel<<<1, 32>>>();
    gate_kernel<<<N_TOK / 32, 256>>>(x, Wg, bg);
    convert_we_kernel<<<(N_EXP * O_DIM * H_DIM) / 512, 256>>>(We);
    scatter_kernel<<<N_TOK / 256, 256>>>();

    dim3 grid(O_DIM / TN, N_TOK / TM + N_EXP);
    moe_gemm_mma<<<grid, 256, SM_TOTAL>>>(be, out);
}